// round 15
// baseline (speedup 1.0000x reference)
#include <cuda_runtime.h>
#include <math.h>
#include <stdint.h>
#include <mma.h>

using namespace nvcuda;

#define HW 128
#define NPAIR 128           // 128 packed complex images (a + i*b)
#define KTOT 16384          // HW*HW
#define GSLICES 64          // split-K slices for gram
#define GKC 256             // K per slice (per CTA)
#define LDS 36              // smem row stride (32 + 4 pad), floats

// ---- scratch (device globals: allocation-free) ----
__device__ float g_psd[NPAIR * KTOT];            // per-pair |F_a|^2+|F_b|^2 (8 MB)
__device__ float g_gram[GSLICES * 128 * 128];    // split-K gram partials (4 MB)
__device__ float g_psd_p1[8 * KTOT];             // stage-1 psd partials (512 KB)
__device__ float g_gram_p1[8 * KTOT];            // stage-1 gram partials (512 KB)
__device__ float g_norm[256];                    // row squared norms (a then b)
__device__ float g_rowvals[128];                 // diag log-prob per row
__device__ float g_psd_part[256];                // [0:64) sum(log avg), [128:192) sum(avg)
__device__ int   g_tail_ctr;                     // tail completion counter (self-resetting)

// =====================================================================
// complex helpers
// =====================================================================
__device__ __forceinline__ float2 cadd(float2 a, float2 b) { return make_float2(a.x + b.x, a.y + b.y); }
__device__ __forceinline__ float2 csub(float2 a, float2 b) { return make_float2(a.x - b.x, a.y - b.y); }
__device__ __forceinline__ float2 cmul(float2 a, float2 w) {
    return make_float2(a.x * w.x - a.y * w.y, a.x * w.y + a.y * w.x);
}

// =====================================================================
// 2D FFT of packed z = a + i*b. Radix-2 DIF, 7 stages split 4+3.
// No bit reversal; PSD via conjugate symmetry; norms fused into load.
// One block per pair, 1024 threads.
// =====================================================================
#define FFT_SMEM ((128 * 129 + 64) * (int)sizeof(float2))

template<int S>
__device__ __forceinline__ void fft_levelA(float2* d, int j0, const float2* tw) {
    float2 u[16];
    #pragma unroll
    for (int m = 0; m < 16; ++m) u[m] = d[(j0 + 8 * m) * S];
    float2 a[16];
    #pragma unroll
    for (int m = 0; m < 8; ++m) {
        a[m]     = cadd(u[m], u[m + 8]);
        a[m + 8] = cmul(csub(u[m], u[m + 8]), tw[j0 + 8 * m]);
    }
    float2 b[16];
    #pragma unroll
    for (int g = 0; g < 2; ++g) {
        #pragma unroll
        for (int m = 0; m < 4; ++m) {
            int lo = g * 8 + m;
            float2 w = tw[2 * (j0 + 8 * m)];
            b[lo]     = cadd(a[lo], a[lo + 4]);
            b[lo + 4] = cmul(csub(a[lo], a[lo + 4]), w);
        }
    }
    float2 c[16];
    #pragma unroll
    for (int g = 0; g < 4; ++g) {
        #pragma unroll
        for (int m = 0; m < 2; ++m) {
            int lo = g * 4 + m;
            float2 w = tw[4 * j0 + 32 * m];
            c[lo]     = cadd(b[lo], b[lo + 2]);
            c[lo + 2] = cmul(csub(b[lo], b[lo + 2]), w);
        }
    }
    float2 w8 = tw[8 * j0];
    #pragma unroll
    for (int m = 0; m < 16; m += 2) {
        float2 t0 = cadd(c[m], c[m + 1]);
        float2 t1 = cmul(csub(c[m], c[m + 1]), w8);
        d[(j0 + 8 * m) * S]       = t0;
        d[(j0 + 8 * (m + 1)) * S] = t1;
    }
}

template<int S>
__device__ __forceinline__ void fft_levelB(float2* d, int q, const float2* tw) {
    float2 v[8];
    #pragma unroll
    for (int k = 0; k < 8; ++k) v[k] = d[(q + k) * S];
    float2 a[8];
    #pragma unroll
    for (int k = 0; k < 4; ++k) {
        a[k]     = cadd(v[k], v[k + 4]);
        a[k + 4] = cmul(csub(v[k], v[k + 4]), tw[16 * k]);
    }
    float2 b[8];
    #pragma unroll
    for (int g = 0; g < 2; ++g) {
        #pragma unroll
        for (int k = 0; k < 2; ++k) {
            int lo = g * 4 + k;
            b[lo]     = cadd(a[lo], a[lo + 2]);
            b[lo + 2] = cmul(csub(a[lo], a[lo + 2]), tw[32 * k]);
        }
    }
    #pragma unroll
    for (int k = 0; k < 8; k += 2) {
        d[(q + k) * S]     = cadd(b[k], b[k + 1]);
        d[(q + k + 1) * S] = csub(b[k], b[k + 1]);
    }
}

__global__ __launch_bounds__(1024, 1)
void fft_psd_kernel(const float* __restrict__ x1, const float* __restrict__ x2) {
    extern __shared__ float2 sm[];
    float2* data = sm;                 // 128 * 129
    float2* tw   = sm + 128 * 129;     // 64 twiddles
    __shared__ int   msk[128];
    __shared__ float redn[64];

    const int t    = threadIdx.x;
    const int line = t & 127;
    const int j0   = t >> 7;           // 0..7
    const int img  = blockIdx.x;
    const float* sa = x1 + (size_t)img * KTOT;
    const float* sb = x2 + (size_t)img * KTOT;

    if (t < 64) {
        float s, c;
        sincosf(-6.283185307179586f * (float)t * (1.0f / 128.0f), &s, &c);
        tw[t] = make_float2(c, s);
    }
    if (t < 128) {
        unsigned r = __brev((unsigned)t) >> 25;
        unsigned n = (128u - r) & 127u;
        msk[t] = (int)(__brev(n) >> 25);
    }

    float na = 0.0f, nb = 0.0f;
    #pragma unroll
    for (int v = t; v < 4096; v += 1024) {
        float4 va = ((const float4*)sa)[v];
        float4 vb = ((const float4*)sb)[v];
        na += va.x * va.x + va.y * va.y + va.z * va.z + va.w * va.w;
        nb += vb.x * vb.x + vb.y * vb.y + vb.z * vb.z + vb.w * vb.w;
        int i = v >> 5;
        int j = (v & 31) * 4;
        float2* base = data + i * 129 + j;
        base[0] = make_float2(va.x, vb.x);
        base[1] = make_float2(va.y, vb.y);
        base[2] = make_float2(va.z, vb.z);
        base[3] = make_float2(va.w, vb.w);
    }
    #pragma unroll
    for (int o = 16; o > 0; o >>= 1) {
        na += __shfl_xor_sync(0xFFFFFFFFu, na, o);
        nb += __shfl_xor_sync(0xFFFFFFFFu, nb, o);
    }
    if ((t & 31) == 0) { redn[t >> 5] = na; redn[32 + (t >> 5)] = nb; }
    __syncthreads();
    if (t == 0) {
        float ta = 0.0f, tb = 0.0f;
        #pragma unroll
        for (int w = 0; w < 32; ++w) { ta += redn[w]; tb += redn[32 + w]; }
        g_norm[img] = ta;
        g_norm[128 + img] = tb;
    }

    {   // pass 1: rows
        float2* d = data + line * 129;
        fft_levelA<1>(d, j0, tw);
        __syncthreads();
        fft_levelB<1>(d, j0 * 16, tw);
        fft_levelB<1>(d, j0 * 16 + 8, tw);
        __syncthreads();
    }
    {   // pass 2: cols
        float2* d = data + line;
        fft_levelA<129>(d, j0, tw);
        __syncthreads();
        fft_levelB<129>(d, j0 * 16, tw);
        fft_levelB<129>(d, j0 * 16 + 8, tw);
        __syncthreads();
    }

    float* dst = g_psd + (size_t)img * KTOT;
    #pragma unroll
    for (int idx = t; idx < KTOT; idx += 1024) {
        int i = idx >> 7, j = idx & 127;
        float2 z1 = data[i * 129 + j];
        float2 z2 = data[msk[i] * 129 + msk[j]];
        dst[idx] = 0.5f * (z1.x * z1.x + z1.y * z1.y + z2.x * z2.x + z2.y * z2.y);
    }
}

// =====================================================================
// Gram via warp-level wmma tf32 (m16n16k8). G = A * B^T.
// 64 CTAs x 512 thr; one CTA per K-slice of 256. 16 warps in 4x4 grid,
// each computing a 32x32 output tile (acc[2][2]).
// =====================================================================
typedef wmma::fragment<wmma::matrix_a, 16, 16, 8, wmma::precision::tf32, wmma::row_major> AFrag;
typedef wmma::fragment<wmma::matrix_b, 16, 16, 8, wmma::precision::tf32, wmma::col_major> BFrag;
typedef wmma::fragment<wmma::accumulator, 16, 16, 8, float> CFrag;

__global__ __launch_bounds__(512)
void gram_wmma_kernel(const float* __restrict__ A, const float* __restrict__ B) {
    __shared__ float As[128 * LDS];
    __shared__ float Bs[128 * LDS];

    const int tid = threadIdx.x;
    const int wid = tid >> 5;
    const int wr  = wid >> 2;          // 0..3 -> rows 32*wr
    const int wc  = wid & 3;           // 0..3 -> cols 32*wc
    const int k0  = blockIdx.x * GKC;

    CFrag acc[2][2];
    #pragma unroll
    for (int m = 0; m < 2; ++m)
        #pragma unroll
        for (int n = 0; n < 2; ++n) wmma::fill_fragment(acc[m][n], 0.0f);

    for (int kc = 0; kc < GKC; kc += 32) {
        #pragma unroll
        for (int idx = tid; idx < 1024; idx += 512) {
            int row = idx >> 3;
            int q   = idx & 7;
            float4 va = *(const float4*)(A + (size_t)row * KTOT + k0 + kc + q * 4);
            float4 vb = *(const float4*)(B + (size_t)row * KTOT + k0 + kc + q * 4);
            *(float4*)(As + row * LDS + q * 4) = va;
            *(float4*)(Bs + row * LDS + q * 4) = vb;
        }
        __syncthreads();
        #pragma unroll
        for (int kk = 0; kk < 32; kk += 8) {
            AFrag fa[2];
            BFrag fb[2];
            #pragma unroll
            for (int m = 0; m < 2; ++m) {
                wmma::load_matrix_sync(fa[m], As + (wr * 32 + m * 16) * LDS + kk, LDS);
                #pragma unroll
                for (int e = 0; e < fa[m].num_elements; ++e)
                    fa[m].x[e] = wmma::__float_to_tf32(fa[m].x[e]);
            }
            #pragma unroll
            for (int n = 0; n < 2; ++n) {
                wmma::load_matrix_sync(fb[n], Bs + (wc * 32 + n * 16) * LDS + kk, LDS);
                #pragma unroll
                for (int e = 0; e < fb[n].num_elements; ++e)
                    fb[n].x[e] = wmma::__float_to_tf32(fb[n].x[e]);
            }
            #pragma unroll
            for (int m = 0; m < 2; ++m)
                #pragma unroll
                for (int n = 0; n < 2; ++n)
                    wmma::mma_sync(acc[m][n], fa[m], fb[n], acc[m][n]);
        }
        __syncthreads();
    }

    float* G = g_gram + (size_t)blockIdx.x * 16384;
    #pragma unroll
    for (int m = 0; m < 2; ++m)
        #pragma unroll
        for (int n = 0; n < 2; ++n)
            wmma::store_matrix_sync(G + (wr * 32 + m * 16) * 128 + wc * 32 + n * 16,
                                    acc[m][n], 128, wmma::mem_row_major);
}

// =====================================================================
// Stage-1 reduction, float4-vectorized: grid (16, 8, 2) x 256 thr.
// z=0: sum 16 images of g_psd (16 loads); z=1: sum 8 slices of g_gram.
// =====================================================================
__global__ __launch_bounds__(256)
void reduce_stage1_kernel() {
    const int f4 = blockIdx.x * 256 + threadIdx.x;      // float4 column 0..4095
    float4 acc = make_float4(0.f, 0.f, 0.f, 0.f);
    if (blockIdx.z == 0) {
        const float4* src = (const float4*)g_psd;
        const int base = blockIdx.y * 16;
        #pragma unroll
        for (int im = 0; im < 16; ++im) {
            float4 v = src[(size_t)(base + im) * 4096 + f4];
            acc.x += v.x; acc.y += v.y; acc.z += v.z; acc.w += v.w;
        }
        ((float4*)g_psd_p1)[(size_t)blockIdx.y * 4096 + f4] = acc;
    } else {
        const float4* src = (const float4*)g_gram;
        const int base = blockIdx.y * 8;
        #pragma unroll
        for (int im = 0; im < 8; ++im) {
            float4 v = src[(size_t)(base + im) * 4096 + f4];
            acc.x += v.x; acc.y += v.y; acc.z += v.z; acc.w += v.w;
        }
        ((float4*)g_gram_p1)[(size_t)blockIdx.y * 4096 + f4] = acc;
    }
}

// =====================================================================
// Tail (fused, self-finalizing): 192 blocks x 256 thr.
// blocks 0..63: PSD stage 2 (256 freqs each);
// blocks 64..191: dist+softmax, ONE row per block (threads 0-127 active).
// Last block (completion counter) computes the final scalar and resets.
// =====================================================================
__global__ __launch_bounds__(256)
void tail_kernel(float* __restrict__ out) {
    const int b = blockIdx.x;
    const int t = threadIdx.x;
    __shared__ float red[16];

    if (b < 64) {
        // ---- PSD stage 2 ----
        const int f = b * 256 + t;
        float s = 0.0f;
        #pragma unroll
        for (int ig = 0; ig < 8; ++ig) s += g_psd_p1[(size_t)ig * KTOT + f];
        float avg = s * (1.0f / 256.0f);
        float sl = logf(avg), sa = avg;
        #pragma unroll
        for (int o = 16; o > 0; o >>= 1) {
            sl += __shfl_xor_sync(0xFFFFFFFFu, sl, o);
            sa += __shfl_xor_sync(0xFFFFFFFFu, sa, o);
        }
        if ((t & 31) == 0) { red[t >> 5] = sl; red[8 + (t >> 5)] = sa; }
        __syncthreads();
        if (t == 0) {
            float tl = 0.0f, ta = 0.0f;
            #pragma unroll
            for (int w = 0; w < 8; ++w) { tl += red[w]; ta += red[8 + w]; }
            g_psd_part[b]       = tl;
            g_psd_part[128 + b] = ta;
        }
    } else {
        // ---- dist + softmax, one row per block (threads 0-127 active) ----
        const int i = b - 64;
        const int j = t & 127;
        float dist = -1e30f;
        if (t < 128) {
            float g = 0.0f;
            #pragma unroll
            for (int ig = 0; ig < 8; ++ig) g += g_gram_p1[(size_t)ig * KTOT + i * 128 + j];
            float d2 = g_norm[i] + g_norm[128 + j] - 2.0f * g;
            dist = sqrtf(fmaxf(d2, 0.0f));
        }
        float m = dist;
        #pragma unroll
        for (int o = 16; o > 0; o >>= 1) m = fmaxf(m, __shfl_xor_sync(0xFFFFFFFFu, m, o));
        if ((t & 31) == 0) red[t >> 5] = m;
        __syncthreads();
        float bm = fmaxf(fmaxf(red[0], red[1]), fmaxf(red[2], red[3]));
        float e = (t < 128) ? expf(dist - bm) : 0.0f;
        #pragma unroll
        for (int o = 16; o > 0; o >>= 1) e += __shfl_xor_sync(0xFFFFFFFFu, e, o);
        if ((t & 31) == 0) red[8 + (t >> 5)] = e;
        __syncthreads();
        float bs = red[8] + red[9] + red[10] + red[11];

        if (t < 128 && j == i) g_rowvals[i] = dist - (bm + logf(bs));
    }

    // ---- completion counter: last block computes the final scalar ----
    __threadfence();
    __syncthreads();
    __shared__ int s_last;
    if (t == 0) s_last = (atomicAdd(&g_tail_ctr, 1) == 191);
    __syncthreads();
    if (s_last) {
        float rv = (t < 128) ? g_rowvals[t] : 0.0f;
        float p1 = (t < 64) ? g_psd_part[t] : 0.0f;
        float p2 = (t < 64) ? g_psd_part[128 + t] : 0.0f;
        #pragma unroll
        for (int o = 16; o > 0; o >>= 1) {
            rv += __shfl_xor_sync(0xFFFFFFFFu, rv, o);
            p1 += __shfl_xor_sync(0xFFFFFFFFu, p1, o);
            p2 += __shfl_xor_sync(0xFFFFFFFFu, p2, o);
        }
        __shared__ float fr[24];
        int w = t >> 5;
        if ((t & 31) == 0) { fr[w] = rv; fr[8 + w] = p1; fr[16 + w] = p2; }
        __syncthreads();
        if (t == 0) {
            float srv = 0.0f, s1 = 0.0f, s2 = 0.0f;
            #pragma unroll
            for (int q = 0; q < 8; ++q) { srv += fr[q]; s1 += fr[8 + q]; s2 += fr[16 + q]; }
            float ce = -(srv * (1.0f / 128.0f));
            float r  = s1 * (1.0f / 16384.0f) - logf(s2 * (1.0f / 16384.0f));
            out[0] = ce - 0.1f * r;
            g_tail_ctr = 0;          // self-reset for next graph replay
        }
    }
}

// =====================================================================
extern "C" void kernel_launch(void* const* d_in, const int* in_sizes, int n_in,
                              void* d_out, int out_size) {
    const float* x1 = (const float*)d_in[0];
    const float* x2 = (const float*)d_in[1];
    float* out = (float*)d_out;

    cudaFuncSetAttribute(fft_psd_kernel,
                         cudaFuncAttributeMaxDynamicSharedMemorySize, FFT_SMEM);

    fft_psd_kernel<<<NPAIR, 1024, FFT_SMEM>>>(x1, x2);
    gram_wmma_kernel<<<GSLICES, 512>>>(x1, x2);
    reduce_stage1_kernel<<<dim3(16, 8, 2), 256>>>();
    tail_kernel<<<192, 256>>>(out);
}

// round 17
// speedup vs baseline: 1.2462x; 1.2462x over previous
#include <cuda_runtime.h>
#include <math.h>
#include <stdint.h>
#include <mma.h>

using namespace nvcuda;

#define HW 128
#define NPAIR 128           // 128 packed complex images (a + i*b)
#define KTOT 16384          // HW*HW
#define GSLICES 128         // split-K slices for gram
#define GKC 128             // K per slice (per CTA)
#define LDS 36              // smem row stride (32 + 4 pad), floats

// ---- scratch (device globals: allocation-free) ----
__device__ float g_psd[NPAIR * KTOT];            // per-pair |Z|^2 (raw, unpaired) (8 MB)
__device__ float g_gram[GSLICES * 128 * 128];    // split-K gram partials (8 MB)
__device__ float g_psd_p1[8 * KTOT];             // stage-1 psd partials (512 KB)
__device__ float g_gram_p1[8 * KTOT];            // stage-1 gram partials (512 KB)
__device__ float g_norm[256];                    // row squared norms (a then b)
__device__ float g_rowvals[128];                 // diag log-prob per row
__device__ float g_psd_part[256];                // [0:64) sum(log avg), [128:192) sum(avg)
__device__ int   g_tail_ctr;                     // tail completion counter (self-resetting)

// =====================================================================
// complex helpers
// =====================================================================
__device__ __forceinline__ float2 cadd(float2 a, float2 b) { return make_float2(a.x + b.x, a.y + b.y); }
__device__ __forceinline__ float2 csub(float2 a, float2 b) { return make_float2(a.x - b.x, a.y - b.y); }
__device__ __forceinline__ float2 cmul(float2 a, float2 w) {
    return make_float2(a.x * w.x - a.y * w.y, a.x * w.y + a.y * w.x);
}

// slot index of the negated frequency (DIF no-bitrev slot space)
__device__ __forceinline__ int neg_slot(int s) {
    unsigned r = __brev((unsigned)s) >> 25;
    unsigned n = (128u - r) & 127u;
    return (int)(__brev(n) >> 25);
}

// =====================================================================
// 2D FFT of packed z = a + i*b. Radix-2 DIF, 7 stages split 4+3.
// No bit reversal. Writes RAW |Z|^2 (conjugate-symmetry pairing is done
// in the tail: exact, since pairing commutes with the image-sum).
// Norms fused into the float4 load. One block per pair, 1024 threads.
// =====================================================================
#define FFT_SMEM ((128 * 129 + 64) * (int)sizeof(float2))

template<int S>
__device__ __forceinline__ void fft_levelA(float2* d, int j0, const float2* tw) {
    float2 u[16];
    #pragma unroll
    for (int m = 0; m < 16; ++m) u[m] = d[(j0 + 8 * m) * S];
    float2 a[16];
    #pragma unroll
    for (int m = 0; m < 8; ++m) {
        a[m]     = cadd(u[m], u[m + 8]);
        a[m + 8] = cmul(csub(u[m], u[m + 8]), tw[j0 + 8 * m]);
    }
    float2 b[16];
    #pragma unroll
    for (int g = 0; g < 2; ++g) {
        #pragma unroll
        for (int m = 0; m < 4; ++m) {
            int lo = g * 8 + m;
            float2 w = tw[2 * (j0 + 8 * m)];
            b[lo]     = cadd(a[lo], a[lo + 4]);
            b[lo + 4] = cmul(csub(a[lo], a[lo + 4]), w);
        }
    }
    float2 c[16];
    #pragma unroll
    for (int g = 0; g < 4; ++g) {
        #pragma unroll
        for (int m = 0; m < 2; ++m) {
            int lo = g * 4 + m;
            float2 w = tw[4 * j0 + 32 * m];
            c[lo]     = cadd(b[lo], b[lo + 2]);
            c[lo + 2] = cmul(csub(b[lo], b[lo + 2]), w);
        }
    }
    float2 w8 = tw[8 * j0];
    #pragma unroll
    for (int m = 0; m < 16; m += 2) {
        float2 t0 = cadd(c[m], c[m + 1]);
        float2 t1 = cmul(csub(c[m], c[m + 1]), w8);
        d[(j0 + 8 * m) * S]       = t0;
        d[(j0 + 8 * (m + 1)) * S] = t1;
    }
}

template<int S>
__device__ __forceinline__ void fft_levelB(float2* d, int q, const float2* tw) {
    float2 v[8];
    #pragma unroll
    for (int k = 0; k < 8; ++k) v[k] = d[(q + k) * S];
    float2 a[8];
    #pragma unroll
    for (int k = 0; k < 4; ++k) {
        a[k]     = cadd(v[k], v[k + 4]);
        a[k + 4] = cmul(csub(v[k], v[k + 4]), tw[16 * k]);
    }
    float2 b[8];
    #pragma unroll
    for (int g = 0; g < 2; ++g) {
        #pragma unroll
        for (int k = 0; k < 2; ++k) {
            int lo = g * 4 + k;
            b[lo]     = cadd(a[lo], a[lo + 2]);
            b[lo + 2] = cmul(csub(a[lo], a[lo + 2]), tw[32 * k]);
        }
    }
    #pragma unroll
    for (int k = 0; k < 8; k += 2) {
        d[(q + k) * S]     = cadd(b[k], b[k + 1]);
        d[(q + k + 1) * S] = csub(b[k], b[k + 1]);
    }
}

__global__ __launch_bounds__(1024, 1)
void fft_psd_kernel(const float* __restrict__ x1, const float* __restrict__ x2) {
    extern __shared__ float2 sm[];
    float2* data = sm;                 // 128 * 129
    float2* tw   = sm + 128 * 129;     // 64 twiddles
    __shared__ float redn[64];

    const int t    = threadIdx.x;
    const int line = t & 127;
    const int j0   = t >> 7;           // 0..7
    const int img  = blockIdx.x;
    const float* sa = x1 + (size_t)img * KTOT;
    const float* sb = x2 + (size_t)img * KTOT;

    if (t < 64) {
        float s, c;
        sincosf(-6.283185307179586f * (float)t * (1.0f / 128.0f), &s, &c);
        tw[t] = make_float2(c, s);
    }

    float na = 0.0f, nb = 0.0f;
    #pragma unroll
    for (int v = t; v < 4096; v += 1024) {
        float4 va = ((const float4*)sa)[v];
        float4 vb = ((const float4*)sb)[v];
        na += va.x * va.x + va.y * va.y + va.z * va.z + va.w * va.w;
        nb += vb.x * vb.x + vb.y * vb.y + vb.z * vb.z + vb.w * vb.w;
        int i = v >> 5;
        int j = (v & 31) * 4;
        float2* base = data + i * 129 + j;
        base[0] = make_float2(va.x, vb.x);
        base[1] = make_float2(va.y, vb.y);
        base[2] = make_float2(va.z, vb.z);
        base[3] = make_float2(va.w, vb.w);
    }
    #pragma unroll
    for (int o = 16; o > 0; o >>= 1) {
        na += __shfl_xor_sync(0xFFFFFFFFu, na, o);
        nb += __shfl_xor_sync(0xFFFFFFFFu, nb, o);
    }
    if ((t & 31) == 0) { redn[t >> 5] = na; redn[32 + (t >> 5)] = nb; }
    __syncthreads();   // covers data, tw, redn
    if (t == 0) {
        float ta = 0.0f, tb = 0.0f;
        #pragma unroll
        for (int w = 0; w < 32; ++w) { ta += redn[w]; tb += redn[32 + w]; }
        g_norm[img] = ta;
        g_norm[128 + img] = tb;
    }

    {   // pass 1: rows
        float2* d = data + line * 129;
        fft_levelA<1>(d, j0, tw);
        __syncthreads();
        fft_levelB<1>(d, j0 * 16, tw);
        fft_levelB<1>(d, j0 * 16 + 8, tw);
        __syncthreads();
    }
    {   // pass 2: cols
        float2* d = data + line;
        fft_levelA<129>(d, j0, tw);
        __syncthreads();
        fft_levelB<129>(d, j0 * 16, tw);
        fft_levelB<129>(d, j0 * 16 + 8, tw);
        __syncthreads();
    }

    // raw |Z|^2, linear (conflict-free smem reads, coalesced stores)
    float* dst = g_psd + (size_t)img * KTOT;
    #pragma unroll
    for (int idx = t; idx < KTOT; idx += 1024) {
        float2 z = data[(idx >> 7) * 129 + (idx & 127)];
        dst[idx] = z.x * z.x + z.y * z.y;
    }
}

// =====================================================================
// Gram via warp-level wmma tf32 (m16n16k8). G = A * B^T.
// One CTA per K-slice of 128; 8 warps in 4x2 grid, each 32x64 of output.
// =====================================================================
typedef wmma::fragment<wmma::matrix_a, 16, 16, 8, wmma::precision::tf32, wmma::row_major> AFrag;
typedef wmma::fragment<wmma::matrix_b, 16, 16, 8, wmma::precision::tf32, wmma::col_major> BFrag;
typedef wmma::fragment<wmma::accumulator, 16, 16, 8, float> CFrag;

__global__ __launch_bounds__(256)
void gram_wmma_kernel(const float* __restrict__ A, const float* __restrict__ B) {
    __shared__ float As[128 * LDS];
    __shared__ float Bs[128 * LDS];

    const int tid = threadIdx.x;
    const int wid = tid >> 5;
    const int wr  = wid >> 1;
    const int wc  = wid & 1;
    const int k0  = blockIdx.x * GKC;

    CFrag acc[2][4];
    #pragma unroll
    for (int m = 0; m < 2; ++m)
        #pragma unroll
        for (int n = 0; n < 4; ++n) wmma::fill_fragment(acc[m][n], 0.0f);

    for (int kc = 0; kc < GKC; kc += 32) {
        #pragma unroll
        for (int idx = tid; idx < 1024; idx += 256) {
            int row = idx >> 3;
            int q   = idx & 7;
            float4 va = *(const float4*)(A + (size_t)row * KTOT + k0 + kc + q * 4);
            float4 vb = *(const float4*)(B + (size_t)row * KTOT + k0 + kc + q * 4);
            *(float4*)(As + row * LDS + q * 4) = va;
            *(float4*)(Bs + row * LDS + q * 4) = vb;
        }
        __syncthreads();
        #pragma unroll
        for (int kk = 0; kk < 32; kk += 8) {
            AFrag fa[2];
            BFrag fb[4];
            #pragma unroll
            for (int m = 0; m < 2; ++m) {
                wmma::load_matrix_sync(fa[m], As + (wr * 32 + m * 16) * LDS + kk, LDS);
                #pragma unroll
                for (int e = 0; e < fa[m].num_elements; ++e)
                    fa[m].x[e] = wmma::__float_to_tf32(fa[m].x[e]);
            }
            #pragma unroll
            for (int n = 0; n < 4; ++n) {
                wmma::load_matrix_sync(fb[n], Bs + (wc * 64 + n * 16) * LDS + kk, LDS);
                #pragma unroll
                for (int e = 0; e < fb[n].num_elements; ++e)
                    fb[n].x[e] = wmma::__float_to_tf32(fb[n].x[e]);
            }
            #pragma unroll
            for (int m = 0; m < 2; ++m)
                #pragma unroll
                for (int n = 0; n < 4; ++n)
                    wmma::mma_sync(acc[m][n], fa[m], fb[n], acc[m][n]);
        }
        __syncthreads();
    }

    float* G = g_gram + (size_t)blockIdx.x * 16384;
    #pragma unroll
    for (int m = 0; m < 2; ++m)
        #pragma unroll
        for (int n = 0; n < 4; ++n)
            wmma::store_matrix_sync(G + (wr * 32 + m * 16) * 128 + wc * 64 + n * 16,
                                    acc[m][n], 128, wmma::mem_row_major);
}

// =====================================================================
// Stage-1 reduction, float4-vectorized: grid (16, 8, 2) x 256 thr.
// z=0: sum 16 images of g_psd; z=1: sum 16 slices of g_gram.
// =====================================================================
__global__ __launch_bounds__(256)
void reduce_stage1_kernel() {
    const int f4 = blockIdx.x * 256 + threadIdx.x;      // float4 column 0..4095
    const float4* src = blockIdx.z ? (const float4*)g_gram : (const float4*)g_psd;
    float4* dst       = blockIdx.z ? (float4*)g_gram_p1 : (float4*)g_psd_p1;
    const int base = blockIdx.y * 16;
    float4 acc = make_float4(0.f, 0.f, 0.f, 0.f);
    #pragma unroll
    for (int im = 0; im < 16; ++im) {
        float4 v = src[(size_t)(base + im) * 4096 + f4];
        acc.x += v.x; acc.y += v.y; acc.z += v.z; acc.w += v.w;
    }
    dst[(size_t)blockIdx.y * 4096 + f4] = acc;
}

// =====================================================================
// Tail (fused, self-finalizing): 192 blocks x 256 thr.
// blocks 0..63: PSD stage 2 with conjugate-symmetry pairing:
//   avg[f] = (S[f] + S[-f]) * 0.5 / 256, S = image-sum of raw |Z|^2.
// blocks 64..191: dist+softmax, one row per block (threads 0-127).
// Last block (completion counter) computes the final scalar and resets.
// =====================================================================
__global__ __launch_bounds__(256)
void tail_kernel(float* __restrict__ out) {
    const int b = blockIdx.x;
    const int t = threadIdx.x;
    __shared__ float red[16];

    if (b < 64) {
        // ---- PSD stage 2 with pairing ----
        const int f  = b * 256 + t;
        const int fi = f >> 7, fj = f & 127;
        const int pf = neg_slot(fi) * 128 + neg_slot(fj);
        float s = 0.0f, sp = 0.0f;
        #pragma unroll
        for (int ig = 0; ig < 8; ++ig) {
            s  += g_psd_p1[(size_t)ig * KTOT + f];
            sp += g_psd_p1[(size_t)ig * KTOT + pf];
        }
        float avg = (s + sp) * (0.5f / 256.0f);
        float sl = logf(avg), sa = avg;
        #pragma unroll
        for (int o = 16; o > 0; o >>= 1) {
            sl += __shfl_xor_sync(0xFFFFFFFFu, sl, o);
            sa += __shfl_xor_sync(0xFFFFFFFFu, sa, o);
        }
        if ((t & 31) == 0) { red[t >> 5] = sl; red[8 + (t >> 5)] = sa; }
        __syncthreads();
        if (t == 0) {
            float tl = 0.0f, ta = 0.0f;
            #pragma unroll
            for (int w = 0; w < 8; ++w) { tl += red[w]; ta += red[8 + w]; }
            g_psd_part[b]       = tl;
            g_psd_part[128 + b] = ta;
        }
    } else {
        // ---- dist + softmax, one row per block (threads 0-127 active) ----
        const int i = b - 64;
        const int j = t & 127;
        float dist = -1e30f;
        if (t < 128) {
            float g = 0.0f;
            #pragma unroll
            for (int ig = 0; ig < 8; ++ig) g += g_gram_p1[(size_t)ig * KTOT + i * 128 + j];
            float d2 = g_norm[i] + g_norm[128 + j] - 2.0f * g;
            dist = sqrtf(fmaxf(d2, 0.0f));
        }
        float m = dist;
        #pragma unroll
        for (int o = 16; o > 0; o >>= 1) m = fmaxf(m, __shfl_xor_sync(0xFFFFFFFFu, m, o));
        if ((t & 31) == 0) red[t >> 5] = m;
        __syncthreads();
        float bm = fmaxf(fmaxf(red[0], red[1]), fmaxf(red[2], red[3]));
        float e = (t < 128) ? expf(dist - bm) : 0.0f;
        #pragma unroll
        for (int o = 16; o > 0; o >>= 1) e += __shfl_xor_sync(0xFFFFFFFFu, e, o);
        if ((t & 31) == 0) red[8 + (t >> 5)] = e;
        __syncthreads();
        float bs = red[8] + red[9] + red[10] + red[11];

        if (t < 128 && j == i) g_rowvals[i] = dist - (bm + logf(bs));
    }

    // ---- completion counter: last block computes the final scalar ----
    __threadfence();
    __syncthreads();
    __shared__ int s_last;
    if (t == 0) s_last = (atomicAdd(&g_tail_ctr, 1) == 191);
    __syncthreads();
    if (s_last) {
        float rv = (t < 128) ? g_rowvals[t] : 0.0f;
        float p1 = (t < 64) ? g_psd_part[t] : 0.0f;
        float p2 = (t < 64) ? g_psd_part[128 + t] : 0.0f;
        #pragma unroll
        for (int o = 16; o > 0; o >>= 1) {
            rv += __shfl_xor_sync(0xFFFFFFFFu, rv, o);
            p1 += __shfl_xor_sync(0xFFFFFFFFu, p1, o);
            p2 += __shfl_xor_sync(0xFFFFFFFFu, p2, o);
        }
        __shared__ float fr[24];
        int w = t >> 5;
        if ((t & 31) == 0) { fr[w] = rv; fr[8 + w] = p1; fr[16 + w] = p2; }
        __syncthreads();
        if (t == 0) {
            float srv = 0.0f, s1 = 0.0f, s2 = 0.0f;
            #pragma unroll
            for (int q = 0; q < 8; ++q) { srv += fr[q]; s1 += fr[8 + q]; s2 += fr[16 + q]; }
            float ce = -(srv * (1.0f / 128.0f));
            float r  = s1 * (1.0f / 16384.0f) - logf(s2 * (1.0f / 16384.0f));
            out[0] = ce - 0.1f * r;
            g_tail_ctr = 0;          // self-reset for next graph replay
        }
    }
}

// =====================================================================
extern "C" void kernel_launch(void* const* d_in, const int* in_sizes, int n_in,
                              void* d_out, int out_size) {
    const float* x1 = (const float*)d_in[0];
    const float* x2 = (const float*)d_in[1];
    float* out = (float*)d_out;

    cudaFuncSetAttribute(fft_psd_kernel,
                         cudaFuncAttributeMaxDynamicSharedMemorySize, FFT_SMEM);

    fft_psd_kernel<<<NPAIR, 1024, FFT_SMEM>>>(x1, x2);
    gram_wmma_kernel<<<GSLICES, 256>>>(x1, x2);
    reduce_stage1_kernel<<<dim3(16, 8, 2), 256>>>();
    tail_kernel<<<192, 256>>>(out);
}